// round 2
// baseline (speedup 1.0000x reference)
#include <cuda_runtime.h>
#include <cstdint>

#define DEVFN __device__ __forceinline__

// ---------------- problem dims ----------------
#define BM 8192
#define KK 4096
#define NN 2048

// ---------------- tiling ----------------
#define TILE_M 128
#define TILE_N 128
#define KC 64                    // s8 elements of K per stage
#define STAGES 3
#define KTILES (KK / KC)         // 64
#define THREADS 256
#define ROWB 80                  // smem row stride in bytes (conflict-free, 16B-aligned)
#define A_TILE (TILE_M * ROWB)   // 10240
#define STAGE_BYTES (2 * A_TILE) // 20480 (A then B)
#define SMEM_BYTES (STAGES * STAGE_BYTES)  // 61440

// ---------------- scratch ----------------
__device__ __align__(16) int8_t g_Xb[(size_t)BM * KK];   // 32 MB sign(X)  [M,K]
__device__ __align__(16) int8_t g_Wb[(size_t)NN * KK];   //  8 MB sign(W)^T [N,K]
__device__ float g_scale[NN];

// ---------------- helpers ----------------
DEVFN void cpa16(uint32_t dst, const void* src) {
    asm volatile("cp.async.cg.shared.global [%0], [%1], 16;" :: "r"(dst), "l"(src) : "memory");
}
DEVFN void cpa_commit() { asm volatile("cp.async.commit_group;" ::: "memory"); }
template <int N> DEVFN void cpa_wait() {
    asm volatile("cp.async.wait_group %0;" :: "n"(N) : "memory");
}
DEVFN void imma(int* d, const int* a, const int* b) {
    asm volatile(
        "mma.sync.aligned.m16n8k32.row.col.s32.s8.s8.s32 "
        "{%0,%1,%2,%3}, {%4,%5,%6,%7}, {%8,%9}, {%0,%1,%2,%3};"
        : "+r"(d[0]), "+r"(d[1]), "+r"(d[2]), "+r"(d[3])
        : "r"(a[0]), "r"(a[1]), "r"(a[2]), "r"(a[3]), "r"(b[0]), "r"(b[1]));
}
DEVFN int sgn8(float x) { return x > 0.0f ? 1 : (x < 0.0f ? -1 : 0); }

// ---------------- prep kernels ----------------
__global__ void k_prep_x(const float4* __restrict__ X4) {
    int idx = blockIdx.x * blockDim.x + threadIdx.x;          // < BM*KK/4
    float4 v = X4[idx];
    uint32_t p = ((uint32_t)(uint8_t)(int8_t)sgn8(v.x)) |
                 ((uint32_t)(uint8_t)(int8_t)sgn8(v.y) << 8) |
                 ((uint32_t)(uint8_t)(int8_t)sgn8(v.z) << 16) |
                 ((uint32_t)(uint8_t)(int8_t)sgn8(v.w) << 24);
    reinterpret_cast<uint32_t*>(g_Xb)[idx] = p;
}

__global__ void k_prep_w(const float* __restrict__ W) {      // W [K,N] -> g_Wb [N,K]
    __shared__ int8_t t[32][33];
    int n0 = blockIdx.x * 32, k0 = blockIdx.y * 32;
    int tx = threadIdx.x, ty = threadIdx.y;
    t[ty][tx] = (int8_t)sgn8(W[(size_t)(k0 + ty) * NN + n0 + tx]);
    __syncthreads();
    g_Wb[(size_t)(n0 + ty) * KK + k0 + tx] = t[tx][ty];
}

__global__ void k_prep_scale(const float* __restrict__ alpha,
                             const float* __restrict__ betta,
                             const float* __restrict__ gamma) {
    int j = blockIdx.x * blockDim.x + threadIdx.x;            // < NN
    float a = fmaxf(alpha[0], 0.0f);
    float b = fmaxf(betta[j >> 6], 0.0f);
    float g = fmaxf(gamma[j & 63], 0.0f);
    g_scale[j] = a * (b * g);
}

// ---------------- GEMM kernel ----------------
extern __shared__ __align__(16) int8_t dynsmem[];

__global__ void __launch_bounds__(THREADS, 2)
k_gemm(float* __restrict__ out) {
    const int tid = threadIdx.x, wid = tid >> 5, lane = tid & 31;
    const int wm = wid >> 2;            // 0..1  (M warp row, 64 rows)
    const int wn = wid & 3;             // 0..3  (N warp col, 32 cols)
    const int rowin = lane >> 2;        // 0..7
    const int quad = lane & 3;          // 0..3
    const int bm = blockIdx.x, bn = blockIdx.y;

    const uint32_t sm0 = (uint32_t)__cvta_generic_to_shared(dynsmem);

    const int8_t* Abase = g_Xb + (size_t)bm * TILE_M * KK;
    const int8_t* Bbase = g_Wb + (size_t)bn * TILE_N * KK;

    // per-thread cp.async chunk coords: 512 16B chunks per tile, 2 per thread
    const int r0 = tid >> 1, c0 = (tid & 1) * 2;              // rows 0..127, chunk cols {0,1} or {2,3}

    auto load_stage = [&](int kt, int st) {
        const uint32_t sA = sm0 + st * STAGE_BYTES;
        const uint32_t sB = sA + A_TILE;
        const int k0 = kt * KC;
#pragma unroll
        for (int c = 0; c < 2; ++c) {
            cpa16(sA + r0 * ROWB + (c0 + c) * 16, Abase + (size_t)r0 * KK + k0 + (c0 + c) * 16);
            cpa16(sB + r0 * ROWB + (c0 + c) * 16, Bbase + (size_t)r0 * KK + k0 + (c0 + c) * 16);
        }
    };

    // prologue: stages 0..STAGES-2
#pragma unroll
    for (int s = 0; s < STAGES - 1; ++s) { load_stage(s, s); cpa_commit(); }

    int acc[4][4][4];
#pragma unroll
    for (int i = 0; i < 4; ++i)
#pragma unroll
        for (int j = 0; j < 4; ++j)
#pragma unroll
            for (int k = 0; k < 4; ++k) acc[i][j][k] = 0;

    for (int kt = 0; kt < KTILES; ++kt) {
        cpa_wait<STAGES - 2>();
        __syncthreads();
        if (kt + STAGES - 1 < KTILES) load_stage(kt + STAGES - 1, (kt + STAGES - 1) % STAGES);
        cpa_commit();

        const int st = kt % STAGES;
        const uint32_t dummy = 0; (void)dummy;
        const int8_t* sA = dynsmem + st * STAGE_BYTES + (wm * 64 + rowin) * ROWB;
        const int8_t* sB = dynsmem + st * STAGE_BYTES + A_TILE + (wn * 32 + rowin) * ROWB;

#pragma unroll
        for (int ks = 0; ks < 2; ++ks) {
            int a[4][4], b[4][2];
#pragma unroll
            for (int mi = 0; mi < 4; ++mi)
#pragma unroll
                for (int p = 0; p < 4; ++p)
                    a[mi][p] = *reinterpret_cast<const int*>(
                        sA + (mi * 16 + (p & 1) * 8) * ROWB + ks * 32 + (p >> 1) * 16 + quad * 4);
#pragma unroll
            for (int ni = 0; ni < 4; ++ni)
#pragma unroll
                for (int p = 0; p < 2; ++p)
                    b[ni][p] = *reinterpret_cast<const int*>(
                        sB + ni * 8 * ROWB + ks * 32 + p * 16 + quad * 4);
#pragma unroll
            for (int mi = 0; mi < 4; ++mi)
#pragma unroll
                for (int ni = 0; ni < 4; ++ni)
                    imma(acc[mi][ni], a[mi], b[ni]);
        }
        // next iteration's __syncthreads() (after wait) protects stage reuse
    }

    // ---------------- epilogue ----------------
    const int mbase = bm * TILE_M + wm * 64;
    const int nbase = bn * TILE_N + wn * 32;
#pragma unroll
    for (int mi = 0; mi < 4; ++mi) {
        const int m = mbase + mi * 16 + rowin;
#pragma unroll
        for (int ni = 0; ni < 4; ++ni) {
            const int n = nbase + ni * 8 + 2 * quad;
            float2 s = *reinterpret_cast<const float2*>(g_scale + n);
            float2 v0, v1;
            v0.x = (float)acc[mi][ni][0] * s.x;
            v0.y = (float)acc[mi][ni][1] * s.y;
            v1.x = (float)acc[mi][ni][2] * s.x;
            v1.y = (float)acc[mi][ni][3] * s.y;
            *reinterpret_cast<float2*>(out + (size_t)m * NN + n) = v0;
            *reinterpret_cast<float2*>(out + (size_t)(m + 8) * NN + n) = v1;
        }
    }
}

// ---------------- launch ----------------
extern "C" void kernel_launch(void* const* d_in, const int* in_sizes, int n_in,
                              void* d_out, int out_size) {
    const float* X     = (const float*)d_in[0];
    const float* W     = (const float*)d_in[1];
    const float* alpha = (const float*)d_in[2];
    const float* betta = (const float*)d_in[3];
    const float* gamma = (const float*)d_in[4];
    float* out = (float*)d_out;

    static bool attr_set = false;
    if (!attr_set) {
        cudaFuncSetAttribute(k_gemm, cudaFuncAttributeMaxDynamicSharedMemorySize, SMEM_BYTES);
        attr_set = true;
    }

    k_prep_x<<<(BM * KK / 4) / 256, 256>>>((const float4*)X);
    k_prep_w<<<dim3(NN / 32, KK / 32), dim3(32, 32)>>>(W);
    k_prep_scale<<<NN / 256, 256>>>(alpha, betta, gamma);
    k_gemm<<<dim3(BM / TILE_M, NN / TILE_N), THREADS, SMEM_BYTES>>>(out);
}

// round 3
// speedup vs baseline: 1.1038x; 1.1038x over previous
#include <cuda_runtime.h>
#include <cstdint>

#define DEVFN __device__ __forceinline__

// ---------------- problem dims ----------------
#define BM 8192
#define KK 4096
#define NN 2048

// ---------------- tiling ----------------
#define TILE_M 128
#define TILE_N 128
#define KC 64                    // s8 elements of K per stage
#define STAGES 3
#define KTILES (KK / KC)         // 64
#define THREADS 256
#define ROWB 80                  // smem row stride (bank-conflict-free for LDSM, 16B aligned)
#define A_TILE (TILE_M * ROWB)   // 10240
#define STAGE_BYTES (2 * A_TILE) // 20480
#define SMEM_BYTES (STAGES * STAGE_BYTES)  // 61440

// ---------------- scratch ----------------
__device__ __align__(16) int8_t g_Xb[(size_t)BM * KK];   // 32 MB sign(X)  [M,K]
__device__ __align__(16) int8_t g_Wb[(size_t)NN * KK];   //  8 MB sign(W)^T [N,K]
__device__ float g_scale[NN];

// ---------------- helpers ----------------
DEVFN void cpa16(uint32_t dst, const void* src) {
    asm volatile("cp.async.cg.shared.global [%0], [%1], 16;" :: "r"(dst), "l"(src) : "memory");
}
DEVFN void cpa_commit() { asm volatile("cp.async.commit_group;" ::: "memory"); }
template <int N> DEVFN void cpa_wait() {
    asm volatile("cp.async.wait_group %0;" :: "n"(N) : "memory");
}
DEVFN void imma(int* d, const int* a, const int* b) {
    asm volatile(
        "mma.sync.aligned.m16n8k32.row.col.s32.s8.s8.s32 "
        "{%0,%1,%2,%3}, {%4,%5,%6,%7}, {%8,%9}, {%0,%1,%2,%3};"
        : "+r"(d[0]), "+r"(d[1]), "+r"(d[2]), "+r"(d[3])
        : "r"(a[0]), "r"(a[1]), "r"(a[2]), "r"(a[3]), "r"(b[0]), "r"(b[1]));
}
DEVFN void ldsm_x4(int* r, uint32_t addr) {
    asm volatile("ldmatrix.sync.aligned.m8n8.x4.shared.b16 {%0,%1,%2,%3}, [%4];"
                 : "=r"(r[0]), "=r"(r[1]), "=r"(r[2]), "=r"(r[3]) : "r"(addr));
}
DEVFN int sgn8(float x) { return x > 0.0f ? 1 : (x < 0.0f ? -1 : 0); }

// ---------------- prep kernels ----------------
__global__ void k_prep_x(const float4* __restrict__ X4) {
    int idx = blockIdx.x * blockDim.x + threadIdx.x;          // < BM*KK/4
    float4 v = X4[idx];
    uint32_t p = ((uint32_t)(uint8_t)(int8_t)sgn8(v.x)) |
                 ((uint32_t)(uint8_t)(int8_t)sgn8(v.y) << 8) |
                 ((uint32_t)(uint8_t)(int8_t)sgn8(v.z) << 16) |
                 ((uint32_t)(uint8_t)(int8_t)sgn8(v.w) << 24);
    reinterpret_cast<uint32_t*>(g_Xb)[idx] = p;
}

__global__ void k_prep_w(const float* __restrict__ W) {      // W [K,N] -> g_Wb [N,K]
    __shared__ int8_t t[32][33];
    int n0 = blockIdx.x * 32, k0 = blockIdx.y * 32;
    int tx = threadIdx.x, ty = threadIdx.y;
    t[ty][tx] = (int8_t)sgn8(W[(size_t)(k0 + ty) * NN + n0 + tx]);
    __syncthreads();
    g_Wb[(size_t)(n0 + ty) * KK + k0 + tx] = t[tx][ty];
}

__global__ void k_prep_scale(const float* __restrict__ alpha,
                             const float* __restrict__ betta,
                             const float* __restrict__ gamma) {
    int j = blockIdx.x * blockDim.x + threadIdx.x;            // < NN
    float a = fmaxf(alpha[0], 0.0f);
    float b = fmaxf(betta[j >> 6], 0.0f);
    float g = fmaxf(gamma[j & 63], 0.0f);
    g_scale[j] = a * (b * g);
}

// ---------------- GEMM kernel ----------------
extern __shared__ __align__(16) int8_t dynsmem[];

__global__ void __launch_bounds__(THREADS, 2)
k_gemm(float* __restrict__ out) {
    const int tid = threadIdx.x, wid = tid >> 5, lane = tid & 31;
    const int wm = wid >> 2;            // 0..1  (M warp row: 64 rows)
    const int wn = wid & 3;             // 0..3  (N warp col: 32 cols)
    const int rowin = lane >> 2;        // 0..7
    const int quad = lane & 3;          // 0..3
    const int bm = blockIdx.x, bn = blockIdx.y;

    const uint32_t sm0 = (uint32_t)__cvta_generic_to_shared(dynsmem);

    const int8_t* Abase = g_Xb + (size_t)bm * TILE_M * KK;
    const int8_t* Bbase = g_Wb + (size_t)bn * TILE_N * KK;

    // cp.async coords: 512 16B chunks per tile, 2 per thread per tile
    const int r0 = tid >> 1, c0 = (tid & 1) * 2;

    auto load_stage = [&](int kt, int st) {
        const uint32_t sA = sm0 + st * STAGE_BYTES;
        const uint32_t sB = sA + A_TILE;
        const int k0 = kt * KC;
#pragma unroll
        for (int c = 0; c < 2; ++c) {
            cpa16(sA + r0 * ROWB + (c0 + c) * 16, Abase + (size_t)r0 * KK + k0 + (c0 + c) * 16);
            cpa16(sB + r0 * ROWB + (c0 + c) * 16, Bbase + (size_t)r0 * KK + k0 + (c0 + c) * 16);
        }
    };

#pragma unroll
    for (int s = 0; s < STAGES - 1; ++s) { load_stage(s, s); cpa_commit(); }

    // ldmatrix per-lane address offsets
    // A x4: t0 rows0-7/k-lo, t1 rows8-15/k-lo, t2 rows0-7/k-hi, t3 rows8-15/k-hi
    const uint32_t aoff = (uint32_t)((lane & 15) * ROWB + (lane >> 4) * 16);
    // B x4 per ni-pair: t0 n0-7/k-lo, t1 n0-7/k-hi, t2 n8-15/k-lo, t3 n8-15/k-hi
    const uint32_t boff = (uint32_t)(((lane & 7) + (lane >> 4) * 8) * ROWB + ((lane >> 3) & 1) * 16);

    int acc[4][4][4];
#pragma unroll
    for (int i = 0; i < 4; ++i)
#pragma unroll
        for (int j = 0; j < 4; ++j)
#pragma unroll
            for (int k = 0; k < 4; ++k) acc[i][j][k] = 0;

    for (int kt = 0; kt < KTILES; ++kt) {
        cpa_wait<STAGES - 2>();
        __syncthreads();
        if (kt + STAGES - 1 < KTILES) load_stage(kt + STAGES - 1, (kt + STAGES - 1) % STAGES);
        cpa_commit();

        const int st = kt % STAGES;
        const uint32_t sst = sm0 + st * STAGE_BYTES;
        const uint32_t aAddr = sst + (uint32_t)(wm * 64 * ROWB) + aoff;
        const uint32_t bAddr = sst + A_TILE + (uint32_t)(wn * 32 * ROWB) + boff;

#pragma unroll
        for (int ks = 0; ks < 2; ++ks) {
            int b[2][4];                 // b[p] = {b(2p,lo), b(2p,hi), b(2p+1,lo), b(2p+1,hi)}
            ldsm_x4(b[0], bAddr + ks * 32);
            ldsm_x4(b[1], bAddr + 16 * ROWB + ks * 32);
            int a[4][4];
#pragma unroll
            for (int mi = 0; mi < 4; ++mi)
                ldsm_x4(a[mi], aAddr + mi * 16 * ROWB + ks * 32);
#pragma unroll
            for (int mi = 0; mi < 4; ++mi) {
                imma(acc[mi][0], a[mi], &b[0][0]);
                imma(acc[mi][1], a[mi], &b[0][2]);
                imma(acc[mi][2], a[mi], &b[1][0]);
                imma(acc[mi][3], a[mi], &b[1][2]);
            }
        }
    }

    // ---------------- epilogue ----------------
    const int mbase = bm * TILE_M + wm * 64;
    const int nbase = bn * TILE_N + wn * 32;
#pragma unroll
    for (int mi = 0; mi < 4; ++mi) {
        const int m = mbase + mi * 16 + rowin;
#pragma unroll
        for (int ni = 0; ni < 4; ++ni) {
            const int n = nbase + ni * 8 + 2 * quad;
            float2 s = *reinterpret_cast<const float2*>(g_scale + n);
            float2 v0, v1;
            v0.x = (float)acc[mi][ni][0] * s.x;
            v0.y = (float)acc[mi][ni][1] * s.y;
            v1.x = (float)acc[mi][ni][2] * s.x;
            v1.y = (float)acc[mi][ni][3] * s.y;
            *reinterpret_cast<float2*>(out + (size_t)m * NN + n) = v0;
            *reinterpret_cast<float2*>(out + (size_t)(m + 8) * NN + n) = v1;
        }
    }
}

// ---------------- launch ----------------
extern "C" void kernel_launch(void* const* d_in, const int* in_sizes, int n_in,
                              void* d_out, int out_size) {
    const float* X     = (const float*)d_in[0];
    const float* W     = (const float*)d_in[1];
    const float* alpha = (const float*)d_in[2];
    const float* betta = (const float*)d_in[3];
    const float* gamma = (const float*)d_in[4];
    float* out = (float*)d_out;

    cudaFuncSetAttribute(k_gemm, cudaFuncAttributeMaxDynamicSharedMemorySize, SMEM_BYTES);

    k_prep_x<<<(BM * KK / 4) / 256, 256>>>((const float4*)X);
    k_prep_w<<<dim3(NN / 32, KK / 32), dim3(32, 32)>>>(W);
    k_prep_scale<<<NN / 256, 256>>>(alpha, betta, gamma);
    k_gemm<<<dim3(BM / TILE_M, NN / TILE_N), THREADS, SMEM_BYTES>>>(out);
}